// round 1
// baseline (speedup 1.0000x reference)
#include <cuda_runtime.h>
#include <math.h>

// GATClassifier_22033182228597
// Shapes (fixed for this problem instance):
#define N_NODES 25000
#define E_EDGES 400000
#define IN_DIM  128
#define H_HEADS 4
#define F_DIM   64
#define HF      256                       // H*F
#define NH      (N_NODES * H_HEADS)       // 100000
#define EH      (E_EDGES * H_HEADS)       // 1600000
#define NHF     (N_NODES * HF)            // 6400000  (rst size)
#define NHIN    (N_NODES * H_HEADS * IN_DIM) // 12800000 (agg_ori size)
#define EHIN    ((size_t)E_EDGES * H_HEADS * IN_DIM) // 204800000 (out_edge size)
#define NEG_SLOPE 0.2f

// ---------------- device scratch (static allocation; no cudaMalloc) --------
__device__ float g_feat_hf[NHF];   // [N, H*F]  = feat @ W^T
__device__ float g_el[NH];         // [N, H]
__device__ float g_er[NH];         // [N, H]
__device__ float g_a[EH];          // [E, H]  edge logits -> exp -> (divided at use)
__device__ float g_maxv[NH];       // [N, H]  segment max
__device__ float g_sumv[NH];       // [N, H]  segment sum of exp
__device__ float g_agg[NHIN];      // [N, H, IN] aggregated ori features
__device__ float g_rst[NHF];       // [N, H, F] pre-relu aggregate

// ---------------- helpers --------------------------------------------------
__device__ __forceinline__ void red_add_f4(float4* addr, float4 v) {
    asm volatile("red.global.add.v4.f32 [%0], {%1, %2, %3, %4};"
                 :: "l"(addr), "f"(v.x), "f"(v.y), "f"(v.z), "f"(v.w)
                 : "memory");
}

__device__ __forceinline__ void atomicMaxF(float* addr, float v) {
    // order-preserving float max via int max (v>=0) / uint min (v<0)
    if (v >= 0.f) atomicMax((int*)addr, __float_as_int(v));
    else          atomicMin((unsigned int*)addr, __float_as_uint(v));
}

// ---------------- K0: init scratch ----------------------------------------
__global__ void k_init() {
    int idx = blockIdx.x * blockDim.x + threadIdx.x;
    if (idx < NHIN) g_agg[idx] = 0.f;
    if (idx < NHF)  g_rst[idx] = 0.f;
    if (idx < NH) {
        g_maxv[idx] = __int_as_float(0xff800000); // -inf
        g_sumv[idx] = 0.f;
    }
}

// ---------------- K1: feat_hf = feat @ W^T  (M=25000, N=256, K=128) --------
// block: 256 threads, computes a 32-row x 256-col tile.
// Per-thread register tile: 8 rows x 4 cols.
__global__ void k_gemm(const float* __restrict__ feat, const float* __restrict__ W) {
    __shared__ float sW[32 * 260];   // [kk][col], padded stride 260 (float4-aligned)
    __shared__ float sF[32 * 33];    // [row][kk], padded stride 33

    const int tid  = threadIdx.x;
    const int row0 = blockIdx.x * 32;
    const int c0   = (tid & 63) * 4;      // 4 consecutive cols
    const int r0   = (tid >> 6) * 8;      // 8 consecutive rows

    float acc[8][4];
#pragma unroll
    for (int r = 0; r < 8; r++)
#pragma unroll
        for (int c = 0; c < 4; c++) acc[r][c] = 0.f;

    for (int kc = 0; kc < IN_DIM; kc += 32) {
        // load W chunk: 256 cols x 32 k (coalesced along k)
        for (int i = tid; i < 32 * 256; i += 256) {
            int c = i >> 5, kk = i & 31;
            sW[kk * 260 + c] = W[c * IN_DIM + kc + kk];
        }
        // load feat chunk: 32 rows x 32 k (coalesced along k)
        for (int i = tid; i < 32 * 32; i += 256) {
            int r = i >> 5, kk = i & 31;
            int row = row0 + r;
            sF[r * 33 + kk] = (row < N_NODES) ? feat[row * IN_DIM + kc + kk] : 0.f;
        }
        __syncthreads();
#pragma unroll
        for (int kk = 0; kk < 32; kk++) {
            float4 wv = *(const float4*)&sW[kk * 260 + c0];
#pragma unroll
            for (int r = 0; r < 8; r++) {
                float fv = sF[(r0 + r) * 33 + kk];   // warp-broadcast
                acc[r][0] += fv * wv.x;
                acc[r][1] += fv * wv.y;
                acc[r][2] += fv * wv.z;
                acc[r][3] += fv * wv.w;
            }
        }
        __syncthreads();
    }
#pragma unroll
    for (int r = 0; r < 8; r++) {
        int row = row0 + r0 + r;
        if (row < N_NODES) {
            float4 v = make_float4(acc[r][0], acc[r][1], acc[r][2], acc[r][3]);
            *(float4*)&g_feat_hf[row * HF + c0] = v;
        }
    }
}

// ---------------- K2: el/er per (node, head): warp-per-pair ----------------
__global__ void k_elr(const float* __restrict__ al, const float* __restrict__ ar) {
    int wid  = (blockIdx.x * blockDim.x + threadIdx.x) >> 5;
    int lane = threadIdx.x & 31;
    if (wid >= NH) return;
    int n = wid >> 2, h = wid & 3;
    const float2* fh  = (const float2*)&g_feat_hf[n * HF + h * F_DIM];
    const float2* al2 = (const float2*)&al[h * F_DIM];
    const float2* ar2 = (const float2*)&ar[h * F_DIM];
    float2 f = fh[lane], a = al2[lane], b = ar2[lane];
    float sl = f.x * a.x + f.y * a.y;
    float sr = f.x * b.x + f.y * b.y;
#pragma unroll
    for (int o = 16; o; o >>= 1) {
        sl += __shfl_down_sync(0xffffffffu, sl, o);
        sr += __shfl_down_sync(0xffffffffu, sr, o);
    }
    if (lane == 0) { g_el[wid] = sl; g_er[wid] = sr; }
}

// ---------------- K3: edge logits + leaky relu + segment max --------------
__global__ void k_edge_max(const int* __restrict__ src, const int* __restrict__ dst) {
    int idx = blockIdx.x * blockDim.x + threadIdx.x;
    if (idx >= EH) return;
    int e = idx >> 2, h = idx & 3;
    int s = src[e], d = dst[e];
    float x = g_el[s * 4 + h] + g_er[d * 4 + h];
    x = (x > 0.f) ? x : NEG_SLOPE * x;
    g_a[idx] = x;
    atomicMaxF(&g_maxv[d * 4 + h], x);
}

// ---------------- K4: exp(e - max) + segment sum ---------------------------
__global__ void k_edge_exp(const int* __restrict__ dst) {
    int idx = blockIdx.x * blockDim.x + threadIdx.x;
    if (idx >= EH) return;
    int e = idx >> 2, h = idx & 3;
    int d = dst[e];
    float ex = expf(g_a[idx] - g_maxv[d * 4 + h]);
    g_a[idx] = ex;
    atomicAdd(&g_sumv[d * 4 + h], ex);
}

// ---------------- K5: scatter-aggregate (rst & agg_ori), warp-per-edge -----
__global__ void k_scatter(const float* __restrict__ feat,
                          const int* __restrict__ src, const int* __restrict__ dst) {
    int e = (blockIdx.x * blockDim.x + threadIdx.x) >> 5;
    if (e >= E_EDGES) return;
    int lane = threadIdx.x & 31;
    int s = src[e], d = dst[e];

    float w0 = g_a[e * 4 + 0] / g_sumv[d * 4 + 0];
    float w1 = g_a[e * 4 + 1] / g_sumv[d * 4 + 1];
    float w2 = g_a[e * 4 + 2] / g_sumv[d * 4 + 2];
    float w3 = g_a[e * 4 + 3] / g_sumv[d * 4 + 3];

    // rst[d, h, f] += w_h * feat_hf[s, h, f]   (256 floats = 64 float4)
    const float4* fh4 = (const float4*)&g_feat_hf[(size_t)s * HF];
    float4* or4       = (float4*)&g_rst[(size_t)d * HF];
    {
        float wa = (lane < 16) ? w0 : w1;   // j = lane      -> head lane/16
        float wb = (lane < 16) ? w2 : w3;   // j = lane + 32 -> head 2 + lane/16
        float4 v = fh4[lane];
        red_add_f4(or4 + lane, make_float4(v.x * wa, v.y * wa, v.z * wa, v.w * wa));
        v = fh4[lane + 32];
        red_add_f4(or4 + lane + 32, make_float4(v.x * wb, v.y * wb, v.z * wb, v.w * wb));
    }
    // agg[d, h, :] += w_h * feat[s, :]   (128 floats/head = 32 float4)
    const float4 f = ((const float4*)feat)[(size_t)s * 32 + lane];
    float4* ag = (float4*)&g_agg[(size_t)d * (H_HEADS * IN_DIM)];
    red_add_f4(ag + 0 * 32 + lane, make_float4(f.x * w0, f.y * w0, f.z * w0, f.w * w0));
    red_add_f4(ag + 1 * 32 + lane, make_float4(f.x * w1, f.y * w1, f.z * w1, f.w * w1));
    red_add_f4(ag + 2 * 32 + lane, make_float4(f.x * w2, f.y * w2, f.z * w2, f.w * w2));
    red_add_f4(ag + 3 * 32 + lane, make_float4(f.x * w3, f.y * w3, f.z * w3, f.w * w3));
}

// ---------------- K6: relu(rst) -> d_out ----------------------------------
__global__ void k_relu_out(float* __restrict__ out) {
    int idx = blockIdx.x * blockDim.x + threadIdx.x;
    if (idx >= NHF / 4) return;
    float4 v = ((const float4*)g_rst)[idx];
    v.x = fmaxf(v.x, 0.f); v.y = fmaxf(v.y, 0.f);
    v.z = fmaxf(v.z, 0.f); v.w = fmaxf(v.w, 0.f);
    ((float4*)out)[idx] = v;
}

// ---------------- K7: out_edge = |agg[src] - agg[dst]|, warp-per-edge ------
__global__ void k_out_edge(const int* __restrict__ src, const int* __restrict__ dst,
                           float* __restrict__ out_edge) {
    int e = (blockIdx.x * blockDim.x + threadIdx.x) >> 5;
    if (e >= E_EDGES) return;
    int lane = threadIdx.x & 31;
    int s = src[e], d = dst[e];
    const float4* A = (const float4*)g_agg;
    float4* O = (float4*)out_edge + (size_t)e * 128;   // H*IN/4 = 128 float4 per edge
#pragma unroll
    for (int h = 0; h < 4; h++) {
        float4 a = A[(size_t)s * 128 + h * 32 + lane];
        float4 b = A[(size_t)d * 128 + h * 32 + lane];
        float4 r = make_float4(fabsf(a.x - b.x), fabsf(a.y - b.y),
                               fabsf(a.z - b.z), fabsf(a.w - b.w));
        __stcs(&O[h * 32 + lane], r);   // streaming store: don't pollute L2
    }
}

// ---------------- launch ---------------------------------------------------
extern "C" void kernel_launch(void* const* d_in, const int* in_sizes, int n_in,
                              void* d_out, int out_size) {
    (void)in_sizes; (void)n_in;
    const float* feat = (const float*)d_in[0];
    const float* W    = (const float*)d_in[1];
    const float* al   = (const float*)d_in[2];
    const float* ar   = (const float*)d_in[3];
    const int*   src  = (const int*)d_in[4];
    const int*   dst  = (const int*)d_in[5];
    float* out = (float*)d_out;

    // output layout: concat(rst flat [6.4M], out_edge flat [204.8M]); handle
    // out_edge-only defensively.
    bool   has_rst  = ((size_t)out_size > EHIN);
    float* out_edge = out + (has_rst ? NHF : 0);

    k_init<<<(NHIN + 255) / 256, 256>>>();
    k_gemm<<<(N_NODES + 31) / 32, 256>>>(feat, W);
    k_elr<<<(NH * 32 + 255) / 256, 256>>>(al, ar);
    k_edge_max<<<(EH + 255) / 256, 256>>>(src, dst);
    k_edge_exp<<<(EH + 255) / 256, 256>>>(dst);
    k_scatter<<<(E_EDGES * 32 + 255) / 256, 256>>>(feat, src, dst);
    if (has_rst)
        k_relu_out<<<(NHF / 4 + 255) / 256, 256>>>(out);
    k_out_edge<<<(E_EDGES * 32 + 255) / 256, 256>>>(src, dst, out_edge);
}

// round 8
// speedup vs baseline: 1.1200x; 1.1200x over previous
#include <cuda_runtime.h>
#include <math.h>

// GATClassifier_22033182228597 — CSR-by-dst pipeline, no global atomic reductions.
#define N_NODES 25000
#define E_EDGES 400000
#define IN_DIM  128
#define H_HEADS 4
#define F_DIM   64
#define HF      256
#define NH      (N_NODES * H_HEADS)
#define NHF     (N_NODES * HF)                 // 6,400,000
#define NHIN    (N_NODES * H_HEADS * IN_DIM)   // 12,800,000
#define EHIN    ((size_t)E_EDGES * H_HEADS * IN_DIM) // 204,800,000
#define NEG_SLOPE 0.2f
#define CHUNK 64

// ---------------- device scratch ------------------------------------------
__device__ float g_feat_hf[NHF];      // [N, H*F]
__device__ float g_el[NH];            // [N, 4]
__device__ float g_er[NH];            // [N, 4]
__device__ float g_agg[NHIN];         // [N, H, IN]
__device__ int   g_cnt[N_NODES];      // per-dst degree
__device__ int   g_off[N_NODES + 1];  // CSR offsets
__device__ int   g_pos[N_NODES];      // placement cursors
__device__ int   g_eidx[E_EDGES];     // sorted-by-dst -> original edge id
__device__ int   g_esrc[E_EDGES];     // sorted-by-dst -> src node

// ---------------- K0: zero histogram --------------------------------------
__global__ void k_zero() {
    int i = blockIdx.x * blockDim.x + threadIdx.x;
    if (i < N_NODES) g_cnt[i] = 0;
}

// ---------------- K1: histogram of dst ------------------------------------
__global__ void k_hist(const int* __restrict__ dst) {
    int e = blockIdx.x * blockDim.x + threadIdx.x;
    if (e < E_EDGES) atomicAdd(&g_cnt[dst[e]], 1);
}

// ---------------- K2: exclusive scan (single block, 1024 threads) ---------
__global__ void k_scan() {
    __shared__ int part[1024];
    const int CH = (N_NODES + 1023) / 1024;   // 25
    int t = threadIdx.x;
    int base = t * CH;
    int sum = 0;
    for (int i = 0; i < CH; i++) {
        int idx = base + i;
        if (idx < N_NODES) sum += g_cnt[idx];
    }
    part[t] = sum;
    __syncthreads();
    for (int o = 1; o < 1024; o <<= 1) {
        int v = (t >= o) ? part[t - o] : 0;
        __syncthreads();
        part[t] += v;
        __syncthreads();
    }
    int off = (t > 0) ? part[t - 1] : 0;
    for (int i = 0; i < CH; i++) {
        int idx = base + i;
        if (idx <= N_NODES) { g_off[idx] = off; if (idx < N_NODES) g_pos[idx] = off; }
        if (idx < N_NODES) off += g_cnt[idx];
    }
}

// ---------------- K3: place edges into CSR --------------------------------
__global__ void k_place(const int* __restrict__ src, const int* __restrict__ dst) {
    int e = blockIdx.x * blockDim.x + threadIdx.x;
    if (e >= E_EDGES) return;
    int p = atomicAdd(&g_pos[dst[e]], 1);
    g_eidx[p] = e;
    g_esrc[p] = src[e];
}

// ---------------- K4: feat_hf = feat @ W^T --------------------------------
__global__ void k_gemm(const float* __restrict__ feat, const float* __restrict__ W) {
    __shared__ float sW[32 * 260];
    __shared__ float sF[32 * 33];
    const int tid  = threadIdx.x;
    const int row0 = blockIdx.x * 32;
    const int c0   = (tid & 63) * 4;
    const int r0   = (tid >> 6) * 8;

    float acc[8][4];
#pragma unroll
    for (int r = 0; r < 8; r++)
#pragma unroll
        for (int c = 0; c < 4; c++) acc[r][c] = 0.f;

    for (int kc = 0; kc < IN_DIM; kc += 32) {
        for (int i = tid; i < 32 * 256; i += 256) {
            int c = i >> 5, kk = i & 31;
            sW[kk * 260 + c] = W[c * IN_DIM + kc + kk];
        }
        for (int i = tid; i < 32 * 32; i += 256) {
            int r = i >> 5, kk = i & 31;
            int row = row0 + r;
            sF[r * 33 + kk] = (row < N_NODES) ? feat[row * IN_DIM + kc + kk] : 0.f;
        }
        __syncthreads();
#pragma unroll
        for (int kk = 0; kk < 32; kk++) {
            float4 wv = *(const float4*)&sW[kk * 260 + c0];
#pragma unroll
            for (int r = 0; r < 8; r++) {
                float fv = sF[(r0 + r) * 33 + kk];
                acc[r][0] += fv * wv.x;
                acc[r][1] += fv * wv.y;
                acc[r][2] += fv * wv.z;
                acc[r][3] += fv * wv.w;
            }
        }
        __syncthreads();
    }
#pragma unroll
    for (int r = 0; r < 8; r++) {
        int row = row0 + r0 + r;
        if (row < N_NODES)
            *(float4*)&g_feat_hf[row * HF + c0] =
                make_float4(acc[r][0], acc[r][1], acc[r][2], acc[r][3]);
    }
}

// ---------------- K5: el/er -----------------------------------------------
__global__ void k_elr(const float* __restrict__ al, const float* __restrict__ ar) {
    int wid  = (blockIdx.x * blockDim.x + threadIdx.x) >> 5;
    int lane = threadIdx.x & 31;
    if (wid >= NH) return;
    int n = wid >> 2, h = wid & 3;
    const float2* fh  = (const float2*)&g_feat_hf[n * HF + h * F_DIM];
    const float2* al2 = (const float2*)&al[h * F_DIM];
    const float2* ar2 = (const float2*)&ar[h * F_DIM];
    float2 f = fh[lane], a = al2[lane], b = ar2[lane];
    float sl = f.x * a.x + f.y * a.y;
    float sr = f.x * b.x + f.y * b.y;
#pragma unroll
    for (int o = 16; o; o >>= 1) {
        sl += __shfl_down_sync(0xffffffffu, sl, o);
        sr += __shfl_down_sync(0xffffffffu, sr, o);
    }
    if (lane == 0) { g_el[wid] = sl; g_er[wid] = sr; }
}

__device__ __forceinline__ float lrelu(float x) {
    return (x > 0.f) ? x : NEG_SLOPE * x;
}

// ---------------- K6: fused softmax + aggregation, one block per dst ------
__global__ __launch_bounds__(256) void k_agg(const float* __restrict__ feat,
                                             float* __restrict__ out_rst) {
    const int d   = blockIdx.x;
    const int tid = threadIdx.x;
    const int beg = g_off[d], end = g_off[d + 1];

    __shared__ float s_red[8][4];
    __shared__ float s_max[4], s_inv[4];
    __shared__ float s_w[CHUNK][4];
    __shared__ int   s_src[CHUNK];

    const float4 er4 = *(const float4*)&g_er[d * 4];

    // ---- pass A: per-head max of leaky-relu logits -------------------
    float m0 = -INFINITY, m1 = -INFINITY, m2 = -INFINITY, m3 = -INFINITY;
    for (int i = beg + tid; i < end; i += 256) {
        int s = g_esrc[i];
        float4 el4 = *(const float4*)&g_el[s * 4];
        m0 = fmaxf(m0, lrelu(el4.x + er4.x));
        m1 = fmaxf(m1, lrelu(el4.y + er4.y));
        m2 = fmaxf(m2, lrelu(el4.z + er4.z));
        m3 = fmaxf(m3, lrelu(el4.w + er4.w));
    }
#pragma unroll
    for (int o = 16; o; o >>= 1) {
        m0 = fmaxf(m0, __shfl_xor_sync(0xffffffffu, m0, o));
        m1 = fmaxf(m1, __shfl_xor_sync(0xffffffffu, m1, o));
        m2 = fmaxf(m2, __shfl_xor_sync(0xffffffffu, m2, o));
        m3 = fmaxf(m3, __shfl_xor_sync(0xffffffffu, m3, o));
    }
    if ((tid & 31) == 0) {
        int w = tid >> 5;
        s_red[w][0] = m0; s_red[w][1] = m1; s_red[w][2] = m2; s_red[w][3] = m3;
    }
    __syncthreads();
    if (tid < 4) {
        float m = s_red[0][tid];
#pragma unroll
        for (int w = 1; w < 8; w++) m = fmaxf(m, s_red[w][tid]);
        s_max[tid] = m;
    }
    __syncthreads();
    const float mx0 = s_max[0], mx1 = s_max[1], mx2 = s_max[2], mx3 = s_max[3];

    // ---- pass B: per-head sum of exp ---------------------------------
    float z0 = 0.f, z1 = 0.f, z2 = 0.f, z3 = 0.f;
    for (int i = beg + tid; i < end; i += 256) {
        int s = g_esrc[i];
        float4 el4 = *(const float4*)&g_el[s * 4];
        z0 += __expf(lrelu(el4.x + er4.x) - mx0);
        z1 += __expf(lrelu(el4.y + er4.y) - mx1);
        z2 += __expf(lrelu(el4.z + er4.z) - mx2);
        z3 += __expf(lrelu(el4.w + er4.w) - mx3);
    }
#pragma unroll
    for (int o = 16; o; o >>= 1) {
        z0 += __shfl_xor_sync(0xffffffffu, z0, o);
        z1 += __shfl_xor_sync(0xffffffffu, z1, o);
        z2 += __shfl_xor_sync(0xffffffffu, z2, o);
        z3 += __shfl_xor_sync(0xffffffffu, z3, o);
    }
    if ((tid & 31) == 0) {
        int w = tid >> 5;
        s_red[w][0] = z0; s_red[w][1] = z1; s_red[w][2] = z2; s_red[w][3] = z3;
    }
    __syncthreads();
    if (tid < 4) {
        float z = s_red[0][tid];
#pragma unroll
        for (int w = 1; w < 8; w++) z += s_red[w][tid];
        s_inv[tid] = 1.f / z;
    }
    __syncthreads();
    const float iv0 = s_inv[0], iv1 = s_inv[1], iv2 = s_inv[2], iv3 = s_inv[3];

    // ---- pass C: chunked weighted accumulation, 4x unrolled ----------
    float racc = 0.f, a1 = 0.f, a2 = 0.f;
    const int h_r  = tid >> 6;        // head for rst position
    const int i_f  = tid & 127;       // feat column
    const int h_a1 = tid >> 7;        // 0/1
    const int h_a2 = 2 + (tid >> 7);  // 2/3

    for (int c = beg; c < end; c += CHUNK) {
        int m = min(CHUNK, end - c);
        if (tid < m) {
            int s = g_esrc[c + tid];
            s_src[tid] = s;
            float4 el4 = *(const float4*)&g_el[s * 4];
            s_w[tid][0] = __expf(lrelu(el4.x + er4.x) - mx0) * iv0;
            s_w[tid][1] = __expf(lrelu(el4.y + er4.y) - mx1) * iv1;
            s_w[tid][2] = __expf(lrelu(el4.z + er4.z) - mx2) * iv2;
            s_w[tid][3] = __expf(lrelu(el4.w + er4.w) - mx3) * iv3;
        }
        __syncthreads();
        int j = 0;
        for (; j + 3 < m; j += 4) {
            int s0 = s_src[j], s1 = s_src[j + 1], s2 = s_src[j + 2], s3 = s_src[j + 3];
            // issue all 8 gathers up front (MLP ~8)
            float g0 = __ldg(&g_feat_hf[(size_t)s0 * HF + tid]);
            float g1 = __ldg(&g_feat_hf[(size_t)s1 * HF + tid]);
            float g2 = __ldg(&g_feat_hf[(size_t)s2 * HF + tid]);
            float g3 = __ldg(&g_feat_hf[(size_t)s3 * HF + tid]);
            float f0 = __ldg(&feat[(size_t)s0 * IN_DIM + i_f]);
            float f1 = __ldg(&feat[(size_t)s1 * IN_DIM + i_f]);
            float f2 = __ldg(&feat[(size_t)s2 * IN_DIM + i_f]);
            float f3 = __ldg(&feat[(size_t)s3 * IN_DIM + i_f]);
            racc += s_w[j][h_r] * g0 + s_w[j + 1][h_r] * g1
                  + s_w[j + 2][h_r] * g2 + s_w[j + 3][h_r] * g3;
            a1   += s_w[j][h_a1] * f0 + s_w[j + 1][h_a1] * f1
                  + s_w[j + 2][h_a1] * f2 + s_w[j + 3][h_a1] * f3;
            a2   += s_w[j][h_a2] * f0 + s_w[j + 1][h_a2] * f1
                  + s_w[j + 2][h_a2] * f2 + s_w[j + 3][h_a2] * f3;
        }
        for (; j < m; j++) {
            int s = s_src[j];
            racc += s_w[j][h_r] * __ldg(&g_feat_hf[(size_t)s * HF + tid]);
            float f = __ldg(&feat[(size_t)s * IN_DIM + i_f]);
            a1 += s_w[j][h_a1] * f;
            a2 += s_w[j][h_a2] * f;
        }
        __syncthreads();
    }
    out_rst[(size_t)d * HF + tid] = fmaxf(racc, 0.f);
    g_agg[(size_t)d * 512 + tid]       = a1;
    g_agg[(size_t)d * 512 + 256 + tid] = a2;
}

// ---------------- K7: out_edge = |agg[src]-agg[dst]|, block per dst -------
// Software-pipelined: prefetch next (e, s) and next src row while storing
// the current one, so the dependent-load chain (esrc -> gather) overlaps.
__global__ __launch_bounds__(256) void k_oe(float* __restrict__ out_edge) {
    const int d   = blockIdx.x;
    const int beg = g_off[d], end = g_off[d + 1];
    if (beg == end) return;
    const int tid = threadIdx.x;
    __shared__ float2 s_d[256];
    const float2* A = (const float2*)g_agg;
    s_d[tid] = A[(size_t)d * 256 + tid];
    __syncthreads();
    const float2 b = s_d[tid];

    int e_cur = g_eidx[beg];
    int s_cur = g_esrc[beg];
    float2 a_cur = A[(size_t)s_cur * 256 + tid];

    for (int i = beg; i < end; i++) {
        int e_nxt = 0, s_nxt = 0;
        float2 a_nxt = make_float2(0.f, 0.f);
        if (i + 1 < end) {
            e_nxt = g_eidx[i + 1];
            s_nxt = g_esrc[i + 1];
            a_nxt = A[(size_t)s_nxt * 256 + tid];   // issue before consuming a_cur
        }
        float2 r = make_float2(fabsf(a_cur.x - b.x), fabsf(a_cur.y - b.y));
        __stcs((float2*)out_edge + (size_t)e_cur * 256 + tid, r);
        e_cur = e_nxt; s_cur = s_nxt; a_cur = a_nxt;
    }
}

// ---------------- launch ---------------------------------------------------
extern "C" void kernel_launch(void* const* d_in, const int* in_sizes, int n_in,
                              void* d_out, int out_size) {
    (void)in_sizes; (void)n_in;
    const float* feat = (const float*)d_in[0];
    const float* W    = (const float*)d_in[1];
    const float* al   = (const float*)d_in[2];
    const float* ar   = (const float*)d_in[3];
    const int*   src  = (const int*)d_in[4];
    const int*   dst  = (const int*)d_in[5];
    float* out = (float*)d_out;

    bool   has_rst  = ((size_t)out_size > EHIN);
    float* out_edge = out + (has_rst ? NHF : 0);
    float* rst_dst  = out;   // rst occupies the front of d_out when present

    k_zero<<<(N_NODES + 255) / 256, 256>>>();
    k_hist<<<(E_EDGES + 255) / 256, 256>>>(dst);
    k_gemm<<<(N_NODES + 31) / 32, 256>>>(feat, W);      // independent of sort
    k_scan<<<1, 1024>>>();
    k_place<<<(E_EDGES + 255) / 256, 256>>>(src, dst);
    k_elr<<<(NH * 32 + 255) / 256, 256>>>(al, ar);
    k_agg<<<N_NODES, 256>>>(feat, rst_dst);
    k_oe<<<N_NODES, 256>>>(out_edge);
    (void)has_rst;
}